// round 1
// baseline (speedup 1.0000x reference)
#include <cuda_runtime.h>
#include <cuda_bf16.h>
#include <math.h>

#define NN    50000
#define EE    800000
#define ETOT  (EE + NN)     // 850000, self loops appended
#define FIN   78
#define H1C   10
#define D1    (H1C * FIN)   // 780
#define OUT2C 128
#define GC    512
#define SLOPE 0.2f

// ---------------- scratch (device globals: allocation-free) ----------------
__device__ float g_h1 [(size_t)NN * D1];     // x @ W1 (messages, layer 1)
__device__ float g_o1 [(size_t)NN * D1];     // aggregated layer-1 output
__device__ float g_as1[(size_t)NN * H1C];
__device__ float g_ad1[(size_t)NN * H1C];
__device__ float g_m1 [(size_t)NN * H1C];
__device__ float g_dn1[(size_t)NN * H1C];
__device__ float g_h2 [(size_t)NN * OUT2C];
__device__ float g_o2 [(size_t)NN * OUT2C];
__device__ float g_as2[NN];
__device__ float g_ad2[NN];
__device__ float g_m2 [NN];
__device__ float g_dn2[NN];
__device__ float g_pool[GC * OUT2C];

// ---------------- helpers ----------------
__device__ __forceinline__ void atomicMaxF(float* addr, float val) {
    if (!signbit(val)) atomicMax((int*)addr, __float_as_int(val));
    else               atomicMin((unsigned int*)addr, __float_as_uint(val));
}

__device__ __forceinline__ void edge_nodes(const int* __restrict__ ei, int t, int& s, int& d) {
    if (t < EE) { s = ei[t]; d = ei[EE + t]; }
    else        { s = t - EE; d = t - EE; }
}

__global__ void fillk(float* p, float v, int n) {
    int i = blockIdx.x * blockDim.x + threadIdx.x;
    if (i < n) p[i] = v;
}

// ---------------- SGEMM: C[M,N] = A[M,K] @ B[K,N] ----------------
// 64x64 block tile, BK=16, 256 threads, 4x4 per-thread microtile.
__global__ __launch_bounds__(256) void sgemm(
    const float* __restrict__ A, const float* __restrict__ B, float* __restrict__ C,
    int M, int K, int Nn)
{
    __shared__ float As[16][64 + 1];
    __shared__ float Bs[16][64 + 1];
    int tid = threadIdx.x;
    int tx = tid & 15, ty = tid >> 4;
    int rowBase = blockIdx.y * 64, colBase = blockIdx.x * 64;
    float acc[4][4] = {};
    for (int k0 = 0; k0 < K; k0 += 16) {
        #pragma unroll
        for (int i = 0; i < 4; i++) {
            int idx = tid + i * 256;
            int r = idx >> 4, c = idx & 15;
            int gr = rowBase + r, gc = k0 + c;
            As[c][r] = (gr < M && gc < K) ? A[(size_t)gr * K + gc] : 0.f;
        }
        #pragma unroll
        for (int i = 0; i < 4; i++) {
            int idx = tid + i * 256;
            int r = idx >> 6, c = idx & 63;
            int gr = k0 + r, gc = colBase + c;
            Bs[r][c] = (gr < K && gc < Nn) ? B[(size_t)gr * Nn + gc] : 0.f;
        }
        __syncthreads();
        #pragma unroll
        for (int k = 0; k < 16; k++) {
            float a[4], bv[4];
            #pragma unroll
            for (int i = 0; i < 4; i++) a[i] = As[k][ty * 4 + i];
            #pragma unroll
            for (int j = 0; j < 4; j++) bv[j] = Bs[k][tx * 4 + j];
            #pragma unroll
            for (int i = 0; i < 4; i++)
                #pragma unroll
                for (int j = 0; j < 4; j++) acc[i][j] += a[i] * bv[j];
        }
        __syncthreads();
    }
    #pragma unroll
    for (int i = 0; i < 4; i++) {
        int gr = rowBase + ty * 4 + i;
        if (gr >= M) continue;
        #pragma unroll
        for (int j = 0; j < 4; j++) {
            int gc = colBase + tx * 4 + j;
            if (gc < Nn) C[(size_t)gr * Nn + gc] = acc[i][j];
        }
    }
}

// ---------------- per-node attention projections ----------------
// warp per (node, head); dual dot-product with shuffle reduce
__global__ void alpha_proj(const float* __restrict__ h,
                           const float* __restrict__ a_src, const float* __restrict__ a_dst,
                           float* __restrict__ as, float* __restrict__ ad,
                           int n, int heads, int dim)
{
    int gw = (blockIdx.x * blockDim.x + threadIdx.x) >> 5;
    int lane = threadIdx.x & 31;
    if (gw >= n * heads) return;
    int node = gw / heads, hd = gw - node * heads;
    const float* hp = h + (size_t)node * heads * dim + (size_t)hd * dim;
    float s1 = 0.f, s2 = 0.f;
    for (int f = lane; f < dim; f += 32) {
        float v = hp[f];
        s1 += v * a_src[hd * dim + f];
        s2 += v * a_dst[hd * dim + f];
    }
    #pragma unroll
    for (int o = 16; o; o >>= 1) {
        s1 += __shfl_down_sync(0xffffffffu, s1, o);
        s2 += __shfl_down_sync(0xffffffffu, s2, o);
    }
    if (lane == 0) { as[gw] = s1; ad[gw] = s2; }
}

// ---------------- edge passes ----------------
__global__ void edge_max(const int* __restrict__ ei, const float* __restrict__ as,
                         const float* __restrict__ ad, float* __restrict__ m, int heads)
{
    int t = blockIdx.x * blockDim.x + threadIdx.x;
    if (t >= ETOT * heads) return;
    int e = t / heads, hd = t - e * heads;
    int s, d; edge_nodes(ei, e, s, d);
    float v = as[s * heads + hd] + ad[d * heads + hd];
    v = v > 0.f ? v : SLOPE * v;
    atomicMaxF(&m[d * heads + hd], v);
}

__global__ void edge_sum(const int* __restrict__ ei, const float* __restrict__ as,
                         const float* __restrict__ ad, const float* __restrict__ m,
                         float* __restrict__ den, int heads)
{
    int t = blockIdx.x * blockDim.x + threadIdx.x;
    if (t >= ETOT * heads) return;
    int e = t / heads, hd = t - e * heads;
    int s, d; edge_nodes(ei, e, s, d);
    float v = as[s * heads + hd] + ad[d * heads + hd];
    v = v > 0.f ? v : SLOPE * v;
    atomicAdd(&den[d * heads + hd], expf(v - m[d * heads + hd]));
}

// warp per (edge, head); lanes stride features
__global__ void edge_scatter(const int* __restrict__ ei, const float* __restrict__ as,
                             const float* __restrict__ ad, const float* __restrict__ m,
                             const float* __restrict__ den, const float* __restrict__ hsrc,
                             float* __restrict__ out, int heads, int dim)
{
    int gw = (blockIdx.x * blockDim.x + threadIdx.x) >> 5;
    int lane = threadIdx.x & 31;
    if (gw >= ETOT * heads) return;
    int e = gw / heads, hd = gw - e * heads;
    int s, d; edge_nodes(ei, e, s, d);
    float v = as[s * heads + hd] + ad[d * heads + hd];
    v = v > 0.f ? v : SLOPE * v;
    float alpha = expf(v - m[d * heads + hd]) / (den[d * heads + hd] + 1e-16f);
    const float* hp = hsrc + (size_t)s * heads * dim + (size_t)hd * dim;
    float*       op = out  + (size_t)d * heads * dim + (size_t)hd * dim;
    for (int f = lane; f < dim; f += 32)
        atomicAdd(&op[f], hp[f] * alpha);
}

// ---------------- bias + relu (in place) ----------------
__global__ void bias_relu(float* __restrict__ o, const float* __restrict__ b, int n, int dim)
{
    int i = blockIdx.x * blockDim.x + threadIdx.x;
    if (i >= n * dim) return;
    int c = i % dim;
    float v = o[i] + b[c];
    o[i] = v > 0.f ? v : 0.f;
}

// ---------------- global max pool ----------------
__global__ void pool_max(const float* __restrict__ o2, const int* __restrict__ batch,
                         float* __restrict__ pool)
{
    int i = blockIdx.x * blockDim.x + threadIdx.x;
    if (i >= NN * OUT2C) return;
    int n = i >> 7, f = i & 127;
    atomicMaxF(&pool[batch[n] * OUT2C + f], o2[i]);
}

// ---------------- final FC (clamps -inf pool entries to 0) ----------------
__global__ __launch_bounds__(OUT2C) void fc_kernel(
    const float* __restrict__ pool, const float* __restrict__ W,
    const float* __restrict__ b, float* __restrict__ out)
{
    __shared__ float p[OUT2C];
    int g = blockIdx.x, j = threadIdx.x;
    float v = pool[g * OUT2C + j];
    p[j] = isfinite(v) ? v : 0.f;
    __syncthreads();
    float acc = b[j];
    #pragma unroll 8
    for (int k = 0; k < OUT2C; k++) acc += p[k] * W[k * OUT2C + j];
    out[g * OUT2C + j] = acc > 0.f ? acc : 0.f;
}

// ---------------- launch ----------------
static inline int cdiv(int a, int b) { return (a + b - 1) / b; }

extern "C" void kernel_launch(void* const* d_in, const int* in_sizes, int n_in,
                              void* d_out, int out_size)
{
    const float* x     = (const float*)d_in[0];
    const int*   ei    = (const int*)  d_in[1];
    const int*   batch = (const int*)  d_in[2];
    // d_in[3] = num_graphs (compile-time GC)
    const float* W1    = (const float*)d_in[4];
    const float* a_s1  = (const float*)d_in[5];
    const float* a_d1  = (const float*)d_in[6];
    const float* b1    = (const float*)d_in[7];
    const float* W2    = (const float*)d_in[8];
    const float* a_s2  = (const float*)d_in[9];
    const float* a_d2  = (const float*)d_in[10];
    const float* b2    = (const float*)d_in[11];
    const float* fcW   = (const float*)d_in[12];
    const float* fcb   = (const float*)d_in[13];
    float* out = (float*)d_out;

    float *h1, *o1, *as1, *ad1, *m1, *dn1, *h2, *o2, *as2, *ad2, *m2, *dn2, *pool;
    cudaGetSymbolAddress((void**)&h1,  g_h1);
    cudaGetSymbolAddress((void**)&o1,  g_o1);
    cudaGetSymbolAddress((void**)&as1, g_as1);
    cudaGetSymbolAddress((void**)&ad1, g_ad1);
    cudaGetSymbolAddress((void**)&m1,  g_m1);
    cudaGetSymbolAddress((void**)&dn1, g_dn1);
    cudaGetSymbolAddress((void**)&h2,  g_h2);
    cudaGetSymbolAddress((void**)&o2,  g_o2);
    cudaGetSymbolAddress((void**)&as2, g_as2);
    cudaGetSymbolAddress((void**)&ad2, g_ad2);
    cudaGetSymbolAddress((void**)&m2,  g_m2);
    cudaGetSymbolAddress((void**)&dn2, g_dn2);
    cudaGetSymbolAddress((void**)&pool, g_pool);

    const float NEG_INF = -INFINITY;

    // init scratch
    fillk<<<cdiv(NN * D1,    256), 256>>>(o1,  0.f,     NN * D1);
    fillk<<<cdiv(NN * H1C,   256), 256>>>(m1,  NEG_INF, NN * H1C);
    fillk<<<cdiv(NN * H1C,   256), 256>>>(dn1, 0.f,     NN * H1C);
    fillk<<<cdiv(NN * OUT2C, 256), 256>>>(o2,  0.f,     NN * OUT2C);
    fillk<<<cdiv(NN,         256), 256>>>(m2,  NEG_INF, NN);
    fillk<<<cdiv(NN,         256), 256>>>(dn2, 0.f,     NN);
    fillk<<<cdiv(GC * OUT2C, 256), 256>>>(pool, NEG_INF, GC * OUT2C);

    // ---- layer 1 ----
    {
        dim3 grid(cdiv(D1, 64), cdiv(NN, 64));
        sgemm<<<grid, 256>>>(x, W1, h1, NN, FIN, D1);
    }
    alpha_proj<<<cdiv(NN * H1C * 32, 256), 256>>>(h1, a_s1, a_d1, as1, ad1, NN, H1C, FIN);
    edge_max  <<<cdiv(ETOT * H1C, 256), 256>>>(ei, as1, ad1, m1, H1C);
    edge_sum  <<<cdiv(ETOT * H1C, 256), 256>>>(ei, as1, ad1, m1, dn1, H1C);
    edge_scatter<<<cdiv(ETOT * H1C * 32, 256), 256>>>(ei, as1, ad1, m1, dn1, h1, o1, H1C, FIN);
    bias_relu <<<cdiv(NN * D1, 256), 256>>>(o1, b1, NN, D1);

    // ---- layer 2 ----
    {
        dim3 grid(cdiv(OUT2C, 64), cdiv(NN, 64));
        sgemm<<<grid, 256>>>(o1, W2, h2, NN, D1, OUT2C);
    }
    alpha_proj<<<cdiv(NN * 32, 256), 256>>>(h2, a_s2, a_d2, as2, ad2, NN, 1, OUT2C);
    edge_max  <<<cdiv(ETOT, 256), 256>>>(ei, as2, ad2, m2, 1);
    edge_sum  <<<cdiv(ETOT, 256), 256>>>(ei, as2, ad2, m2, dn2, 1);
    edge_scatter<<<cdiv(ETOT * 32, 256), 256>>>(ei, as2, ad2, m2, dn2, h2, o2, 1, OUT2C);
    bias_relu <<<cdiv(NN * OUT2C, 256), 256>>>(o2, b2, NN, OUT2C);

    // ---- pool + fc ----
    pool_max<<<cdiv(NN * OUT2C, 256), 256>>>(o2, batch, pool);
    fc_kernel<<<GC, OUT2C>>>(pool, fcW, fcb, out);
}

// round 3
// speedup vs baseline: 2.5676x; 2.5676x over previous
#include <cuda_runtime.h>
#include <cuda_bf16.h>
#include <math.h>

#define NN    50000
#define EE    800000
#define ETOT  (EE + NN)
#define FIN   78
#define H1C   10
#define D1    (H1C * FIN)   // 780
#define OUT2C 128
#define GC    512
#define SLOPE 0.2f
#define CHUNK 64

// ---------------- scratch ----------------
__device__ float g_h1 [(size_t)NN * D1];
__device__ float g_o1 [(size_t)NN * D1];
__device__ float g_h2 [(size_t)NN * OUT2C];
__device__ float g_o2 [(size_t)NN * OUT2C];
__device__ float g_as1[(size_t)NN * H1C];
__device__ float g_ad1[(size_t)NN * H1C];
__device__ float g_as2[NN];
__device__ float g_ad2[NN];
__device__ int   g_deg[NN + 1];
__device__ int   g_rowptr[NN + 1];
__device__ int   g_cursor[NN];
__device__ int   g_csrsrc[ETOT];
__device__ int   g_gstart[GC + 1];

// ---------------- helpers ----------------
__device__ __forceinline__ void atomicMaxF(float* addr, float val) {
    if (!signbit(val)) atomicMax((int*)addr, __float_as_int(val));
    else               atomicMin((unsigned int*)addr, __float_as_uint(val));
}
__device__ __forceinline__ void edge_nodes(const int* __restrict__ ei, int t, int& s, int& d) {
    if (t < EE) { s = ei[t]; d = ei[EE + t]; }
    else        { s = t - EE; d = t - EE; }
}

__global__ void fill_int(int* p, int v, int n) {
    int i = blockIdx.x * blockDim.x + threadIdx.x;
    if (i < n) p[i] = v;
}

// ---------------- CSR build ----------------
__global__ void hist_kernel(const int* __restrict__ ei, int* __restrict__ deg) {
    int t = blockIdx.x * blockDim.x + threadIdx.x;
    if (t >= ETOT) return;
    int s, d; edge_nodes(ei, t, s, d);
    atomicAdd(&deg[d], 1);
}

__global__ void scan50k(const int* __restrict__ deg, int* __restrict__ rowptr) {
    __shared__ int sh[1024];
    __shared__ int carry_s;
    int tid = threadIdx.x;
    if (tid == 0) carry_s = 0;
    __syncthreads();
    for (int base = 0; base < NN; base += 1024) {
        int i = base + tid;
        int v = (i < NN) ? deg[i] : 0;
        sh[tid] = v;
        __syncthreads();
        #pragma unroll
        for (int o = 1; o < 1024; o <<= 1) {
            int t = (tid >= o) ? sh[tid - o] : 0;
            __syncthreads();
            sh[tid] += t;
            __syncthreads();
        }
        int c = carry_s;
        if (i < NN) rowptr[i] = c + sh[tid] - v;
        __syncthreads();
        if (tid == 0) carry_s = c + sh[1023];
        __syncthreads();
    }
    if (tid == 0) rowptr[NN] = carry_s;
}

__global__ void cursor_copy(const int* __restrict__ rowptr, int* __restrict__ cur) {
    int i = blockIdx.x * blockDim.x + threadIdx.x;
    if (i < NN) cur[i] = rowptr[i];
}

__global__ void csr_scatter(const int* __restrict__ ei, int* __restrict__ cur,
                            int* __restrict__ csrsrc) {
    int t = blockIdx.x * blockDim.x + threadIdx.x;
    if (t >= ETOT) return;
    int s, d; edge_nodes(ei, t, s, d);
    int pos = atomicAdd(&cur[d], 1);
    csrsrc[pos] = s;
}

__global__ void gstart_build(const int* __restrict__ batch, int* __restrict__ gstart) {
    int i = blockIdx.x * blockDim.x + threadIdx.x;
    if (i >= NN) return;
    int b  = batch[i];
    int bp = (i == 0) ? -1 : batch[i - 1];
    for (int g = bp + 1; g <= b; ++g) gstart[g] = i;
    if (i == NN - 1) {
        for (int g = b + 1; g <= GC; ++g) gstart[g] = NN;
    }
}

// ---------------- SGEMM: C[M,N] = A[M,K] @ B[K,N], 128x128x16, 8x8 micro ----
__global__ __launch_bounds__(256) void sgemm128(
    const float* __restrict__ A, const float* __restrict__ B, float* __restrict__ C,
    int M, int K, int Nn)
{
    __shared__ float As[16][132];
    __shared__ float Bs[16][132];
    int tid = threadIdx.x;
    int tx = tid & 15, ty = tid >> 4;
    int rowBase = blockIdx.y * 128, colBase = blockIdx.x * 128;
    float acc[8][8] = {};
    for (int k0 = 0; k0 < K; k0 += 16) {
        #pragma unroll
        for (int i = 0; i < 8; i++) {
            int idx = tid + i * 256;
            int r = idx >> 4, c = idx & 15;
            int gr = rowBase + r, gc = k0 + c;
            As[c][r] = (gr < M && gc < K) ? A[(size_t)gr * K + gc] : 0.f;
        }
        #pragma unroll
        for (int i = 0; i < 8; i++) {
            int idx = tid + i * 256;
            int r = idx >> 7, c = idx & 127;
            int gr = k0 + r, gc = colBase + c;
            Bs[r][c] = (gr < K && gc < Nn) ? B[(size_t)gr * Nn + gc] : 0.f;
        }
        __syncthreads();
        #pragma unroll
        for (int k = 0; k < 16; k++) {
            float a[8], b[8];
            #pragma unroll
            for (int i = 0; i < 8; i++) a[i] = As[k][ty * 8 + i];
            #pragma unroll
            for (int j = 0; j < 8; j++) b[j] = Bs[k][tx * 8 + j];
            #pragma unroll
            for (int i = 0; i < 8; i++)
                #pragma unroll
                for (int j = 0; j < 8; j++) acc[i][j] += a[i] * b[j];
        }
        __syncthreads();
    }
    #pragma unroll
    for (int i = 0; i < 8; i++) {
        int gr = rowBase + ty * 8 + i;
        if (gr >= M) continue;
        #pragma unroll
        for (int j = 0; j < 8; j++) {
            int gc = colBase + tx * 8 + j;
            if (gc < Nn) C[(size_t)gr * Nn + gc] = acc[i][j];
        }
    }
}

// ---------------- per-node attention projections ----------------
__global__ void alpha_proj(const float* __restrict__ h,
                           const float* __restrict__ a_src, const float* __restrict__ a_dst,
                           float* __restrict__ as, float* __restrict__ ad,
                           int n, int heads, int dim)
{
    int gw = (blockIdx.x * blockDim.x + threadIdx.x) >> 5;
    int lane = threadIdx.x & 31;
    if (gw >= n * heads) return;
    int node = gw / heads, hd = gw - node * heads;
    const float* hp = h + (size_t)node * heads * dim + (size_t)hd * dim;
    float s1 = 0.f, s2 = 0.f;
    for (int f = lane; f < dim; f += 32) {
        float v = hp[f];
        s1 += v * a_src[hd * dim + f];
        s2 += v * a_dst[hd * dim + f];
    }
    #pragma unroll
    for (int o = 16; o; o >>= 1) {
        s1 += __shfl_down_sync(0xffffffffu, s1, o);
        s2 += __shfl_down_sync(0xffffffffu, s2, o);
    }
    if (lane == 0) { as[gw] = s1; ad[gw] = s2; }
}

// ---------------- layer-1 gather (10 heads, 78 feats) ----------------
__global__ __launch_bounds__(256) void gat_gather1(
    const int* __restrict__ rowptr, const int* __restrict__ csrsrc,
    const float* __restrict__ as, const float* __restrict__ ad,
    const float* __restrict__ h, const float* __restrict__ bias,
    float* __restrict__ out)
{
    int d = blockIdx.x;
    int tid = threadIdx.x;
    int beg = rowptr[d], end = rowptr[d + 1];
    int deg = end - beg;

    __shared__ float m[H1C];
    __shared__ float den[H1C];
    __shared__ float adv[H1C];
    __shared__ int   s_src[CHUNK];
    __shared__ float w[CHUNK][H1C];

    if (tid < H1C) {
        adv[tid] = ad[d * H1C + tid];
        m[tid] = -INFINITY;
        den[tid] = 0.f;
    }
    __syncthreads();

    // pass A: per-head max over incoming edges
    for (int t = tid; t < deg * H1C; t += 256) {
        int e = t / H1C, hh = t - e * H1C;
        int s = csrsrc[beg + e];
        float v = as[s * H1C + hh] + adv[hh];
        v = v > 0.f ? v : SLOPE * v;
        atomicMaxF(&m[hh], v);
    }
    __syncthreads();

    int f0 = tid, f1 = tid + 256, f2 = tid + 512, f3 = tid + 768;
    int hh0 = f0 / FIN, hh1 = f1 / FIN, hh2 = f2 / FIN;
    int hh3 = (f3 < D1) ? f3 / FIN : 0;
    float acc0 = 0.f, acc1 = 0.f, acc2 = 0.f, acc3 = 0.f;

    for (int cbeg = 0; cbeg < deg; cbeg += CHUNK) {
        int clen = min(CHUNK, deg - cbeg);
        for (int t = tid; t < clen; t += 256) s_src[t] = csrsrc[beg + cbeg + t];
        __syncthreads();
        for (int t = tid; t < clen * H1C; t += 256) {
            int e = t / H1C, hh = t - e * H1C;
            float v = as[s_src[e] * H1C + hh] + adv[hh];
            v = v > 0.f ? v : SLOPE * v;
            float ww = __expf(v - m[hh]);
            w[e][hh] = ww;
            atomicAdd(&den[hh], ww);
        }
        __syncthreads();
        for (int e = 0; e < clen; e++) {
            const float* row = h + (size_t)s_src[e] * D1;
            acc0 += row[f0] * w[e][hh0];
            acc1 += row[f1] * w[e][hh1];
            acc2 += row[f2] * w[e][hh2];
            if (f3 < D1) acc3 += row[f3] * w[e][hh3];
        }
        __syncthreads();
    }

    float* op = out + (size_t)d * D1;
    float v0 = acc0 / (den[hh0] + 1e-16f) + bias[f0];
    float v1 = acc1 / (den[hh1] + 1e-16f) + bias[f1];
    float v2 = acc2 / (den[hh2] + 1e-16f) + bias[f2];
    op[f0] = v0 > 0.f ? v0 : 0.f;
    op[f1] = v1 > 0.f ? v1 : 0.f;
    op[f2] = v2 > 0.f ? v2 : 0.f;
    if (f3 < D1) {
        float v3 = acc3 / (den[hh3] + 1e-16f) + bias[f3];
        op[f3] = v3 > 0.f ? v3 : 0.f;
    }
}

// ---------------- layer-2 gather (1 head, 128 feats) ----------------
#define CHUNK2 128
__global__ __launch_bounds__(128) void gat_gather2(
    const int* __restrict__ rowptr, const int* __restrict__ csrsrc,
    const float* __restrict__ as, const float* __restrict__ ad,
    const float* __restrict__ h, const float* __restrict__ bias,
    float* __restrict__ out)
{
    int d = blockIdx.x;
    int tid = threadIdx.x;
    int beg = rowptr[d], end = rowptr[d + 1];
    int deg = end - beg;

    __shared__ float ms, dens;
    __shared__ int   s_src[CHUNK2];
    __shared__ float w[CHUNK2];

    float adv = ad[d];
    if (tid == 0) { ms = -INFINITY; dens = 0.f; }
    __syncthreads();

    for (int t = tid; t < deg; t += 128) {
        float v = as[csrsrc[beg + t]] + adv;
        v = v > 0.f ? v : SLOPE * v;
        atomicMaxF(&ms, v);
    }
    __syncthreads();
    float mv = ms;
    float acc = 0.f;

    for (int cbeg = 0; cbeg < deg; cbeg += CHUNK2) {
        int clen = min(CHUNK2, deg - cbeg);
        if (tid < clen) {
            int s = csrsrc[beg + cbeg + tid];
            s_src[tid] = s;
            float v = as[s] + adv;
            v = v > 0.f ? v : SLOPE * v;
            float ww = __expf(v - mv);
            w[tid] = ww;
            atomicAdd(&dens, ww);
        }
        __syncthreads();
        for (int e = 0; e < clen; e++)
            acc += h[(size_t)s_src[e] * OUT2C + tid] * w[e];
        __syncthreads();
    }

    float v = acc / (dens + 1e-16f) + bias[tid];
    out[(size_t)d * OUT2C + tid] = v > 0.f ? v : 0.f;
}

// ---------------- fused pool(max) + fc + relu ----------------
__global__ __launch_bounds__(128) void pool_fc(
    const float* __restrict__ o2, const int* __restrict__ gstart,
    const float* __restrict__ W, const float* __restrict__ b,
    float* __restrict__ out)
{
    __shared__ float p[OUT2C];
    int g = blockIdx.x, j = threadIdx.x;
    int beg = gstart[g], end = gstart[g + 1];
    float acc = -INFINITY;
    for (int n = beg; n < end; n++)
        acc = fmaxf(acc, o2[(size_t)n * OUT2C + j]);
    p[j] = (beg < end) ? acc : 0.f;   // o2 is post-ReLU, finite
    __syncthreads();
    float s = b[j];
    #pragma unroll 8
    for (int k = 0; k < OUT2C; k++) s += p[k] * W[k * OUT2C + j];
    out[g * OUT2C + j] = s > 0.f ? s : 0.f;
}

// ---------------- launch ----------------
static inline int cdiv(int a, int b) { return (a + b - 1) / b; }

extern "C" void kernel_launch(void* const* d_in, const int* in_sizes, int n_in,
                              void* d_out, int out_size)
{
    const float* x     = (const float*)d_in[0];
    const int*   ei    = (const int*)  d_in[1];
    const int*   batch = (const int*)  d_in[2];
    const float* W1    = (const float*)d_in[4];
    const float* a_s1  = (const float*)d_in[5];
    const float* a_d1  = (const float*)d_in[6];
    const float* b1    = (const float*)d_in[7];
    const float* W2    = (const float*)d_in[8];
    const float* a_s2  = (const float*)d_in[9];
    const float* a_d2  = (const float*)d_in[10];
    const float* b2    = (const float*)d_in[11];
    const float* fcW   = (const float*)d_in[12];
    const float* fcb   = (const float*)d_in[13];
    float* out = (float*)d_out;

    float *h1, *o1, *h2, *o2, *as1, *ad1, *as2, *ad2;
    int *deg, *rowptr, *cursor, *csrsrc, *gstart;
    cudaGetSymbolAddress((void**)&h1,  g_h1);
    cudaGetSymbolAddress((void**)&o1,  g_o1);
    cudaGetSymbolAddress((void**)&h2,  g_h2);
    cudaGetSymbolAddress((void**)&o2,  g_o2);
    cudaGetSymbolAddress((void**)&as1, g_as1);
    cudaGetSymbolAddress((void**)&ad1, g_ad1);
    cudaGetSymbolAddress((void**)&as2, g_as2);
    cudaGetSymbolAddress((void**)&ad2, g_ad2);
    cudaGetSymbolAddress((void**)&deg,    g_deg);
    cudaGetSymbolAddress((void**)&rowptr, g_rowptr);
    cudaGetSymbolAddress((void**)&cursor, g_cursor);
    cudaGetSymbolAddress((void**)&csrsrc, g_csrsrc);
    cudaGetSymbolAddress((void**)&gstart, g_gstart);

    // ---- CSR build (reused by both layers) ----
    fill_int<<<cdiv(NN + 1, 256), 256>>>(deg, 0, NN + 1);
    hist_kernel<<<cdiv(ETOT, 256), 256>>>(ei, deg);
    scan50k<<<1, 1024>>>(deg, rowptr);
    cursor_copy<<<cdiv(NN, 256), 256>>>(rowptr, cursor);
    csr_scatter<<<cdiv(ETOT, 256), 256>>>(ei, cursor, csrsrc);
    gstart_build<<<cdiv(NN, 256), 256>>>(batch, gstart);

    // ---- layer 1 ----
    {
        dim3 grid(cdiv(D1, 128), cdiv(NN, 128));
        sgemm128<<<grid, 256>>>(x, W1, h1, NN, FIN, D1);
    }
    alpha_proj<<<cdiv(NN * H1C * 32, 256), 256>>>(h1, a_s1, a_d1, as1, ad1, NN, H1C, FIN);
    gat_gather1<<<NN, 256>>>(rowptr, csrsrc, as1, ad1, h1, b1, o1);

    // ---- layer 2 ----
    {
        dim3 grid(cdiv(OUT2C, 128), cdiv(NN, 128));
        sgemm128<<<grid, 256>>>(o1, W2, h2, NN, D1, OUT2C);
    }
    alpha_proj<<<cdiv(NN * 32, 256), 256>>>(h2, a_s2, a_d2, as2, ad2, NN, 1, OUT2C);
    gat_gather2<<<NN, 128>>>(rowptr, csrsrc, as2, ad2, h2, b2, o2);

    // ---- pool + fc ----
    pool_fc<<<GC, OUT2C>>>(o2, gstart, fcW, fcb, out);
}